// round 7
// baseline (speedup 1.0000x reference)
#include <cuda_runtime.h>
#include <cuda_bf16.h>
#include <cstdint>

// out[b, a*16+c, d, l] = sum_k s[b,(c-a)%16,l,k] * t[b,c,l,d-k]  (linear conv)
// Per (b,c,l): D[128d x 16m] = A[128x64] * B[16x64]^T,
//   A[d][k] = t_pad[d-k] (Toeplitz), B[m][k] = s[b,m,l,k].
// Engine: mma.sync.m16n8k16 bf16 (plain sm_80+ PTX; tcgen05 needs sm_103a
// which the harness ptxas target does not enable). bf16 3-term split
// (hi*hi + hi*lo + lo*hi) for fp32-grade accuracy.
// Banded A: Abar[rr][j] = t_pad[rr-j], rr in [0,80); tile (md,kt) = Abar rows
// 16*(md-kt)...; sigma = md-kt in [0,4] -> full sigma x kt cross product.

typedef unsigned int u32;

#define OFF_A    0
#define A_SIDE   3840          // 80 rows * 48B   (hi / lo halves)
#define A_PERL   7680
#define OFF_B    61440
#define B_SIDE   2304          // 16 rows * 144B
#define B_PERL   4608
#define OFF_TP   98304         // 8 * 96 floats
#define SMEM_TOTAL 101376
#define STG_MS   1156          // staging m-stride (floats): 128*9 + 4
#define STG_DS   9             // staging d-stride (floats): 8 l + 1 pad

__device__ __forceinline__ u32 pack_bf2(float a, float b) {   // low = a, high = b
    u32 r;
    asm("{\n\t.reg .b16 lo, hi;\n\t"
        "cvt.rn.bf16.f32 lo, %1;\n\tcvt.rn.bf16.f32 hi, %2;\n\t"
        "mov.b32 %0, {lo, hi};\n\t}" : "=r"(r) : "f"(a), "f"(b));
    return r;
}
__device__ __forceinline__ float bf_hi(float x) {
    return __bfloat162float(__float2bfloat16(x));
}
__device__ __forceinline__ void mma_bf16(float* c, const u32* a, u32 b0, u32 b1) {
    asm("mma.sync.aligned.m16n8k16.row.col.f32.bf16.bf16.f32 "
        "{%0,%1,%2,%3}, {%4,%5,%6,%7}, {%8,%9}, {%0,%1,%2,%3};"
        : "+f"(c[0]), "+f"(c[1]), "+f"(c[2]), "+f"(c[3])
        : "r"(a[0]), "r"(a[1]), "r"(a[2]), "r"(a[3]), "r"(b0), "r"(b1));
}

__global__ __launch_bounds__(256, 2)
void conv_mma(const float* __restrict__ s_g,
              const float* __restrict__ t_g,
              float* __restrict__ out) {
    extern __shared__ char smem[];
    float* smf = (float*)smem;
    const int tid = threadIdx.x, wid = tid >> 5, lane = tid & 31;
    const int gid = lane >> 2, tig = lane & 3;
    const int lq = blockIdx.x, c = blockIdx.y, b = blockIdx.z;
    const int lbase = lq * 8;

    // ---- zero t_pad staging (zero padding is load-bearing) ----
    float* tp_f = (float*)(smem + OFF_TP);
    for (int i = tid; i < 768; i += 256) tp_f[i] = 0.0f;
    __syncthreads();

    // ---- fill t_pad: tp[l][16 + k] = t[b,c,lbase+l,k]  (STRIDE LOOP: 504 > 256!) ----
    for (int i = tid; i < 504; i += 256) {
        int l = i / 63, k = i - l * 63;
        tp_f[l * 96 + 16 + k] =
            t_g[(((size_t)b * 16 + c) * 64 + lbase + l) * 63 + k];
    }

    // ---- build B: [l][side hi/lo][16 m rows][64 k] bf16, 144B row stride ----
    {
        int h = tid & 1, mrow = tid >> 1, m = mrow & 15, l = mrow >> 4;
        const float* sp = s_g + (((size_t)b * 16 + m) * 64 + lbase + l) * 63 + h * 32;
        u32 hw[16], lw[16];
        #pragma unroll
        for (int q = 0; q < 16; q++) {
            float x0 = sp[2 * q];                    // k = h*32+2q <= 62 always
            float x1 = 0.0f;
            if (h * 32 + 2 * q + 1 < 63) x1 = sp[2 * q + 1];
            float h0 = bf_hi(x0), h1 = bf_hi(x1);
            hw[q] = pack_bf2(h0, h1);
            lw[q] = pack_bf2(x0 - h0, x1 - h1);
        }
        char* bh = smem + OFF_B + l * B_PERL + m * 144 + h * 64;
        char* bl = bh + B_SIDE;
        #pragma unroll
        for (int cc = 0; cc < 4; cc++) {
            *(uint4*)(bh + cc * 16) =
                make_uint4(hw[cc*4], hw[cc*4+1], hw[cc*4+2], hw[cc*4+3]);
            *(uint4*)(bl + cc * 16) =
                make_uint4(lw[cc*4], lw[cc*4+1], lw[cc*4+2], lw[cc*4+3]);
        }
    }
    __syncthreads();

    // ---- build banded A: Abar[l][side][rr][j] = t_pad[rr - j], rr in [0,80) ----
    for (int i = tid; i < 640; i += 256) {
        int l = i / 80, rr = i - (i / 80) * 80;
        const float* tpl = tp_f + l * 96 + 16 + rr;   // tpl[-j] = t_pad[rr-j]
        u32 hw[8], lw[8];
        #pragma unroll
        for (int q = 0; q < 8; q++) {
            float x0 = tpl[-(2 * q)], x1 = tpl[-(2 * q + 1)];
            float h0 = bf_hi(x0), h1 = bf_hi(x1);
            hw[q] = pack_bf2(h0, h1);
            lw[q] = pack_bf2(x0 - h0, x1 - h1);
        }
        char* ah = smem + OFF_A + l * A_PERL + rr * 48;
        char* al = ah + A_SIDE;
        *(uint4*)(ah)      = make_uint4(hw[0], hw[1], hw[2], hw[3]);
        *(uint4*)(ah + 16) = make_uint4(hw[4], hw[5], hw[6], hw[7]);
        *(uint4*)(al)      = make_uint4(lw[0], lw[1], lw[2], lw[3]);
        *(uint4*)(al + 16) = make_uint4(lw[4], lw[5], lw[6], lw[7]);
    }
    __syncthreads();

    // ---- MMA mainloop: warp = l ----
    const int l = wid;
    u32 bfr[4][2][2][2];   // [kt][nt][side][b0/b1] -- all B frags resident
    {
        const char* bb = smem + OFF_B + l * B_PERL;
        #pragma unroll
        for (int kt = 0; kt < 4; kt++)
            #pragma unroll
            for (int nt = 0; nt < 2; nt++)
                #pragma unroll
                for (int sd = 0; sd < 2; sd++) {
                    const char* ad = bb + sd * B_SIDE + (8 * nt + gid) * 144
                                   + kt * 32 + tig * 4;
                    bfr[kt][nt][sd][0] = *(const u32*)ad;
                    bfr[kt][nt][sd][1] = *(const u32*)(ad + 16);
                }
    }

    float acc[8][2][4];
    #pragma unroll
    for (int md = 0; md < 8; md++)
        #pragma unroll
        for (int nt = 0; nt < 2; nt++)
            #pragma unroll
            for (int e = 0; e < 4; e++) acc[md][nt][e] = 0.0f;

    const char* ab = smem + OFF_A + l * A_PERL;
    #pragma unroll
    for (int sg = 0; sg < 5; sg++) {                       // sigma = md - kt
        const char* ar = ab + sg * 768 + gid * 48 + tig * 4;
        u32 ah4[4] = { *(const u32*)ar,        *(const u32*)(ar + 384),
                       *(const u32*)(ar + 16), *(const u32*)(ar + 400) };
        const char* alp = ar + A_SIDE;
        u32 al4[4] = { *(const u32*)alp,        *(const u32*)(alp + 384),
                       *(const u32*)(alp + 16), *(const u32*)(alp + 400) };
        #pragma unroll
        for (int kt = 0; kt < 4; kt++) {
            const int md = sg + kt;                        // 0..7, always valid
            #pragma unroll
            for (int nt = 0; nt < 2; nt++) {
                mma_bf16(acc[md][nt], ah4, bfr[kt][nt][0][0], bfr[kt][nt][0][1]); // hi*hi
                mma_bf16(acc[md][nt], ah4, bfr[kt][nt][1][0], bfr[kt][nt][1][1]); // hi*lo
                mma_bf16(acc[md][nt], al4, bfr[kt][nt][0][0], bfr[kt][nt][0][1]); // lo*hi
            }
        }
    }
    __syncthreads();   // A/B dead; staging overlays smem from offset 0

    // ---- stage accumulators: stage[m*1156 + d*9 + l] ----
    #pragma unroll
    for (int md = 0; md < 8; md++)
        #pragma unroll
        for (int nt = 0; nt < 2; nt++) {
            int d0 = 16 * md + gid, m0 = 8 * nt + 2 * tig;
            float* st = smf + m0 * STG_MS + d0 * STG_DS + l;
            st[0]                    = acc[md][nt][0];
            st[STG_MS]               = acc[md][nt][1];
            st[8 * STG_DS]           = acc[md][nt][2];
            st[STG_MS + 8 * STG_DS]  = acc[md][nt][3];
        }
    __syncthreads();

    // ---- epilogue: lanes vary l fastest -> full 32B store sectors ----
    {
        const int l_off = lane & 7, q = lane >> 3;
        #pragma unroll
        for (int mm = 0; mm < 2; mm++) {
            int m = 2 * wid + mm;
            int a = (c - m) & 15;
            float* ob = out + (((size_t)(b * 256 + a * 16 + c)) << 13)
                      + (size_t)(8 * q) * 64 + lbase + l_off;
            const float* sm_m = smf + m * STG_MS + 72 * q + l_off;
            #pragma unroll
            for (int jj = 0; jj < 32; jj++) {
                int dlo = jj & 7, dhi = jj >> 3;
                ob[(size_t)(dlo + 32 * dhi) * 64] = sm_m[9 * dlo + 288 * dhi];
            }
        }
    }
}

extern "C" void kernel_launch(void* const* d_in, const int* in_sizes, int n_in,
                              void* d_out, int out_size) {
    const float* s = (const float*)d_in[0];
    const float* t = (const float*)d_in[1];
    float* out = (float*)d_out;

    cudaFuncSetAttribute(conv_mma,
                         cudaFuncAttributeMaxDynamicSharedMemorySize, SMEM_TOTAL);

    dim3 grid(8, 16, 32);   // (l-octet, c, b) = 4096 blocks
    conv_mma<<<grid, 256, SMEM_TOTAL>>>(s, t, out);
}

// round 8
// speedup vs baseline: 1.5504x; 1.5504x over previous
#include <cuda_runtime.h>
#include <cuda_bf16.h>
#include <cstdint>

// out[b, a*16+c, d, l] = sum_k s[b,(c-a)%16,l,k] * t[b,c,l,d-k]  (linear conv)
// Per (b,c,l): D[128d x 16m] = A[128x64] * B[16x64]^T,
//   A[d][k] = t_pad[d-k] (Toeplitz), B[m][k] = s[b,m,l,k].
// Engine: mma.sync.m16n8k16 bf16 (sm_80+ PTX; tcgen05 needs the 'a' target).
// bf16 3-term split (hi*hi + hi*lo + lo*hi) for fp32-grade accuracy.
// R7 fix: s tile staged to smem via coalesced float4 LDG (was: 32-line
// uncoalesced LDG per warp instr = the L1 wall at 77%).

typedef unsigned int u32;

#define OFF_A    0
#define A_SIDE   3840          // 80 rows * 48B   (hi / lo halves)
#define A_PERL   7680
#define OFF_B    61440
#define B_SIDE   2304          // 16 rows * 144B
#define B_PERL   4608
#define OFF_TP   98304         // 8 * 96 floats
#define SMEM_TOTAL 101376
#define STG_MS   1156          // staging m-stride (floats)
#define STG_DS   9             // staging d-stride (floats)
#define SRS      519           // s_raw m-stride (floats); 519 mod 32 = 7

__device__ __forceinline__ u32 pack_bf2(float a, float b) {   // low = a, high = b
    u32 r;
    asm("{\n\t.reg .b16 lo, hi;\n\t"
        "cvt.rn.bf16.f32 lo, %1;\n\tcvt.rn.bf16.f32 hi, %2;\n\t"
        "mov.b32 %0, {lo, hi};\n\t}" : "=r"(r) : "f"(a), "f"(b));
    return r;
}
__device__ __forceinline__ float bf_hi(float x) {
    return __bfloat162float(__float2bfloat16(x));
}
__device__ __forceinline__ void mma_bf16(float* c, const u32* a, u32 b0, u32 b1) {
    asm("mma.sync.aligned.m16n8k16.row.col.f32.bf16.bf16.f32 "
        "{%0,%1,%2,%3}, {%4,%5,%6,%7}, {%8,%9}, {%0,%1,%2,%3};"
        : "+f"(c[0]), "+f"(c[1]), "+f"(c[2]), "+f"(c[3])
        : "r"(a[0]), "r"(a[1]), "r"(a[2]), "r"(a[3]), "r"(b0), "r"(b1));
}

__global__ __launch_bounds__(256, 2)
void conv_mma(const float* __restrict__ s_g,
              const float* __restrict__ t_g,
              float* __restrict__ out) {
    extern __shared__ char smem[];
    float* smf = (float*)smem;
    const int tid = threadIdx.x, wid = tid >> 5, lane = tid & 31;
    const int gid = lane >> 2, tig = lane & 3;
    const int lq = blockIdx.x, c = blockIdx.y, b = blockIdx.z;
    const int lbase = lq * 8;

    // ---- zero t_pad staging (zero padding is load-bearing) ----
    float* tp_f = (float*)(smem + OFF_TP);
    for (int i = tid; i < 768; i += 256) tp_f[i] = 0.0f;
    __syncthreads();

    // ---- fill tp (coalesced) + stage s tile (coalesced float4) ----
    for (int i = tid; i < 504; i += 256) {
        int l = i / 63, k = i - l * 63;
        tp_f[l * 96 + 16 + k] =
            t_g[(((size_t)b * 16 + c) * 64 + lbase + l) * 63 + k];
    }
    float* s_raw = smf;                                    // overlays A region
    {
        const float* sgb = s_g + ((size_t)b * 1024 + lbase) * 63;
        for (int i = tid; i < 2016; i += 256) {            // 16 m * 126 float4
            int m = i / 126, j = i - m * 126;
            float4 v = *(const float4*)(sgb + (size_t)m * 4032 + j * 4);
            float* dst = s_raw + m * SRS + j * 4;          // scalar STS (odd stride)
            dst[0] = v.x; dst[1] = v.y; dst[2] = v.z; dst[3] = v.w;
        }
    }
    __syncthreads();

    // ---- build B from s_raw: [l][side hi/lo][16 m rows][64 k] bf16, 144B stride ----
    {
        int h = tid & 1, mrow = tid >> 1, m = mrow & 15, l = mrow >> 4;
        const float* sp = s_raw + m * SRS + l * 63 + h * 32;
        u32 hw[16], lw[16];
        #pragma unroll
        for (int q = 0; q < 16; q++) {
            float x0 = sp[2 * q];                          // k = h*32+2q <= 62
            float x1 = 0.0f;
            if (h * 32 + 2 * q + 1 < 63) x1 = sp[2 * q + 1];
            float h0 = bf_hi(x0), h1 = bf_hi(x1);
            hw[q] = pack_bf2(h0, h1);
            lw[q] = pack_bf2(x0 - h0, x1 - h1);
        }
        char* bh = smem + OFF_B + l * B_PERL + m * 144 + h * 64;
        char* bl = bh + B_SIDE;
        #pragma unroll
        for (int cc = 0; cc < 4; cc++) {
            *(uint4*)(bh + cc * 16) =
                make_uint4(hw[cc*4], hw[cc*4+1], hw[cc*4+2], hw[cc*4+3]);
            *(uint4*)(bl + cc * 16) =
                make_uint4(lw[cc*4], lw[cc*4+1], lw[cc*4+2], lw[cc*4+3]);
        }
    }
    __syncthreads();   // B done reading s_raw; A build may now overwrite it

    // ---- build banded A: Abar[l][side][rr][j] = t_pad[rr - j], rr in [0,80) ----
    for (int i = tid; i < 640; i += 256) {
        int l = i / 80, rr = i - (i / 80) * 80;
        const float* tpl = tp_f + l * 96 + 16 + rr;        // tpl[-j] = t_pad[rr-j]
        u32 hw[8], lw[8];
        #pragma unroll
        for (int q = 0; q < 8; q++) {
            float x0 = tpl[-(2 * q)], x1 = tpl[-(2 * q + 1)];
            float h0 = bf_hi(x0), h1 = bf_hi(x1);
            hw[q] = pack_bf2(h0, h1);
            lw[q] = pack_bf2(x0 - h0, x1 - h1);
        }
        char* ah = smem + OFF_A + l * A_PERL + rr * 48;
        char* al = ah + A_SIDE;
        *(uint4*)(ah)      = make_uint4(hw[0], hw[1], hw[2], hw[3]);
        *(uint4*)(ah + 16) = make_uint4(hw[4], hw[5], hw[6], hw[7]);
        *(uint4*)(al)      = make_uint4(lw[0], lw[1], lw[2], lw[3]);
        *(uint4*)(al + 16) = make_uint4(lw[4], lw[5], lw[6], lw[7]);
    }
    __syncthreads();

    // ---- MMA mainloop: warp = l ----
    const int l = wid;
    u32 bfr[4][2][2][2];   // [kt][nt][side][b0/b1]
    {
        const char* bb = smem + OFF_B + l * B_PERL;
        #pragma unroll
        for (int kt = 0; kt < 4; kt++)
            #pragma unroll
            for (int nt = 0; nt < 2; nt++)
                #pragma unroll
                for (int sd = 0; sd < 2; sd++) {
                    const char* ad = bb + sd * B_SIDE + (8 * nt + gid) * 144
                                   + kt * 32 + tig * 4;
                    bfr[kt][nt][sd][0] = *(const u32*)ad;
                    bfr[kt][nt][sd][1] = *(const u32*)(ad + 16);
                }
    }

    float acc[8][2][4];
    #pragma unroll
    for (int md = 0; md < 8; md++)
        #pragma unroll
        for (int nt = 0; nt < 2; nt++)
            #pragma unroll
            for (int e = 0; e < 4; e++) acc[md][nt][e] = 0.0f;

    const char* ab = smem + OFF_A + l * A_PERL;
    #pragma unroll
    for (int sg = 0; sg < 5; sg++) {                       // sigma = md - kt
        const char* ar = ab + sg * 768 + gid * 48 + tig * 4;
        u32 ah4[4] = { *(const u32*)ar,        *(const u32*)(ar + 384),
                       *(const u32*)(ar + 16), *(const u32*)(ar + 400) };
        const char* alp = ar + A_SIDE;
        u32 al4[4] = { *(const u32*)alp,        *(const u32*)(alp + 384),
                       *(const u32*)(alp + 16), *(const u32*)(alp + 400) };
        #pragma unroll
        for (int kt = 0; kt < 4; kt++) {
            const int md = sg + kt;                        // 0..7
            #pragma unroll
            for (int nt = 0; nt < 2; nt++) {
                mma_bf16(acc[md][nt], ah4, bfr[kt][nt][0][0], bfr[kt][nt][0][1]); // hi*hi
                mma_bf16(acc[md][nt], ah4, bfr[kt][nt][1][0], bfr[kt][nt][1][1]); // hi*lo
                mma_bf16(acc[md][nt], al4, bfr[kt][nt][0][0], bfr[kt][nt][0][1]); // lo*hi
            }
        }
    }
    __syncthreads();   // A/B dead; staging overlays smem from offset 0

    // ---- stage accumulators: stage[m*1156 + d*9 + l] (conflict-free) ----
    #pragma unroll
    for (int md = 0; md < 8; md++)
        #pragma unroll
        for (int nt = 0; nt < 2; nt++) {
            int d0 = 16 * md + gid, m0 = 8 * nt + 2 * tig;
            float* st = smf + m0 * STG_MS + d0 * STG_DS + l;
            st[0]                    = acc[md][nt][0];
            st[STG_MS]               = acc[md][nt][1];
            st[8 * STG_DS]           = acc[md][nt][2];
            st[STG_MS + 8 * STG_DS]  = acc[md][nt][3];
        }
    __syncthreads();

    // ---- epilogue: lanes vary l fastest -> full 32B store sectors ----
    {
        const int l_off = lane & 7, q = lane >> 3;
        #pragma unroll
        for (int mm = 0; mm < 2; mm++) {
            int m = 2 * wid + mm;
            int a = (c - m) & 15;
            float* ob = out + (((size_t)(b * 256 + a * 16 + c)) << 13)
                      + (size_t)(8 * q) * 64 + lbase + l_off;
            const float* sm_m = smf + m * STG_MS + 72 * q + l_off;
            #pragma unroll
            for (int jj = 0; jj < 32; jj++) {
                int dlo = jj & 7, dhi = jj >> 3;
                ob[(size_t)(dlo + 32 * dhi) * 64] = sm_m[9 * dlo + 288 * dhi];
            }
        }
    }
}

extern "C" void kernel_launch(void* const* d_in, const int* in_sizes, int n_in,
                              void* d_out, int out_size) {
    const float* s = (const float*)d_in[0];
    const float* t = (const float*)d_in[1];
    float* out = (float*)d_out;

    cudaFuncSetAttribute(conv_mma,
                         cudaFuncAttributeMaxDynamicSharedMemorySize, SMEM_TOTAL);

    dim3 grid(8, 16, 32);   // (l-octet, c, b) = 4096 blocks
    conv_mma<<<grid, 256, SMEM_TOTAL>>>(s, t, out);
}